// round 1
// baseline (speedup 1.0000x reference)
#include <cuda_runtime.h>

#define GENES 2048
#define HEADS 8
#define BATCH 16
#define NP 13   // Taylor moments: powers 0..12

// Scratch for per-(b,h) moments, pre-scaled by 1/n!
__device__ float g_momA[BATCH * HEADS * NP];
__device__ float g_momB[BATCH * HEADS * NP];

__constant__ float c_invfact[NP] = {
    1.0f, 1.0f, 0.5f,
    1.0f / 6.0f, 1.0f / 24.0f, 1.0f / 120.0f,
    1.0f / 720.0f, 1.0f / 5040.0f, 1.0f / 40320.0f,
    1.0f / 362880.0f, 1.0f / 3628800.0f, 1.0f / 39916800.0f,
    1.0f / 479001600.0f
};

// ---------------------------------------------------------------------------
// Pass 1: one block per (b,h). Compute A_n = sum_i K_i^n, B_n = sum_i K_i^n V_i
// where K_i = x[b,i]*WK[h,i], V_i = x[b,i]*WV[h,i]. Store A_n/n!, B_n/n!.
// ---------------------------------------------------------------------------
__global__ void __launch_bounds__(256)
moments_kernel(const float* __restrict__ x,
               const float* __restrict__ WK,
               const float* __restrict__ WV)
{
    const int bh = blockIdx.x;           // 0..127
    const int b  = bh >> 3;
    const int h  = bh & 7;
    const float* __restrict__ xb = x  + b * GENES;
    const float* __restrict__ wk = WK + h * GENES;
    const float* __restrict__ wv = WV + h * GENES;

    float A[NP], Bm[NP];
#pragma unroll
    for (int n = 0; n < NP; n++) { A[n] = 0.0f; Bm[n] = 0.0f; }

    for (int i = threadIdx.x; i < GENES; i += 256) {
        const float xi = xb[i];
        const float k  = xi * wk[i];
        const float v  = xi * wv[i];
        float p = 1.0f;
#pragma unroll
        for (int n = 0; n < NP; n++) {
            A[n]  += p;
            Bm[n]  = fmaf(p, v, Bm[n]);
            p     *= k;
        }
    }

    // Warp reduction
#pragma unroll
    for (int n = 0; n < NP; n++) {
#pragma unroll
        for (int off = 16; off > 0; off >>= 1) {
            A[n]  += __shfl_xor_sync(0xFFFFFFFFu, A[n],  off);
            Bm[n] += __shfl_xor_sync(0xFFFFFFFFu, Bm[n], off);
        }
    }

    __shared__ float sA[8][NP];
    __shared__ float sB[8][NP];
    const int w    = threadIdx.x >> 5;
    const int lane = threadIdx.x & 31;
    if (lane == 0) {
#pragma unroll
        for (int n = 0; n < NP; n++) { sA[w][n] = A[n]; sB[w][n] = Bm[n]; }
    }
    __syncthreads();

    if (threadIdx.x < NP) {
        const int n = threadIdx.x;
        float a = 0.0f, bb = 0.0f;
#pragma unroll
        for (int ww = 0; ww < 8; ww++) { a += sA[ww][n]; bb += sB[ww][n]; }
        g_momA[bh * NP + n] = a  * c_invfact[n];
        g_momB[bh * NP + n] = bb * c_invfact[n];
    }
}

// ---------------------------------------------------------------------------
// Pass 2: one thread per output element (b,g).
//   q = x[b,g]*WQ[h,g]
//   P0 = sum_n (A_n/n!) q^n   (Horner)
//   P1 = sum_n (B_n/n!) q^n
//   z  = (P1 - exp(q*K_g)*V_g) / P0
//   out[b,g] = sum_h z * W0[h]
// ---------------------------------------------------------------------------
__global__ void __launch_bounds__(256)
attn_out_kernel(const float* __restrict__ x,
                const float* __restrict__ WQ,
                const float* __restrict__ WK,
                const float* __restrict__ WV,
                const float* __restrict__ W0,
                float* __restrict__ out)
{
    const int idx = blockIdx.x * 256 + threadIdx.x;   // 0..32767
    const int b   = idx >> 11;                        // uniform within a block
    const int g   = idx & (GENES - 1);

    __shared__ float sA[HEADS][NP];
    __shared__ float sB[HEADS][NP];
    __shared__ float sW0[HEADS];

    if (threadIdx.x < HEADS * NP) {
        const int h = threadIdx.x / NP;
        const int n = threadIdx.x % NP;
        sA[h][n] = g_momA[(b * HEADS + h) * NP + n];
        sB[h][n] = g_momB[(b * HEADS + h) * NP + n];
    }
    if (threadIdx.x < HEADS) sW0[threadIdx.x] = W0[threadIdx.x];
    __syncthreads();

    const float xg = x[idx];
    float acc = 0.0f;

#pragma unroll
    for (int h = 0; h < HEADS; h++) {
        const float q  = xg * WQ[h * GENES + g];
        const float kg = xg * WK[h * GENES + g];
        const float vg = xg * WV[h * GENES + g];

        float P0 = sA[h][NP - 1];
        float P1 = sB[h][NP - 1];
#pragma unroll
        for (int n = NP - 2; n >= 0; n--) {
            P0 = fmaf(P0, q, sA[h][n]);
            P1 = fmaf(P1, q, sB[h][n]);
        }

        const float e = __expf(q * kg);           // exact diagonal correction
        const float z = (P1 - e * vg) / P0;
        acc = fmaf(z, sW0[h], acc);
    }

    out[idx] = acc;
}

// ---------------------------------------------------------------------------
extern "C" void kernel_launch(void* const* d_in, const int* in_sizes, int n_in,
                              void* d_out, int out_size)
{
    const float* x  = (const float*)d_in[0];
    const float* WQ = (const float*)d_in[1];
    const float* WK = (const float*)d_in[2];
    const float* WV = (const float*)d_in[3];
    const float* W0 = (const float*)d_in[4];
    float* out = (float*)d_out;

    moments_kernel<<<BATCH * HEADS, 256>>>(x, WK, WV);
    attn_out_kernel<<<(BATCH * GENES) / 256, 256>>>(x, WQ, WK, WV, W0, out);
}

// round 2
// speedup vs baseline: 1.1224x; 1.1224x over previous
#include <cuda_runtime.h>

#define GENES 2048
#define HEADS 8
#define BATCH 16
#define NP 13     // Taylor moments: powers 0..12
#define PARTS 4   // partial-sum blocks per (b,h) in the moments pass

// Scratch: per-(b,h,power,part) partial moments, pre-scaled by 1/n!
__device__ float g_momA[BATCH * HEADS * NP * PARTS];
__device__ float g_momB[BATCH * HEADS * NP * PARTS];

__constant__ float c_invfact[NP] = {
    1.0f, 1.0f, 0.5f,
    1.0f / 6.0f, 1.0f / 24.0f, 1.0f / 120.0f,
    1.0f / 720.0f, 1.0f / 5040.0f, 1.0f / 40320.0f,
    1.0f / 362880.0f, 1.0f / 3628800.0f, 1.0f / 39916800.0f,
    1.0f / 479001600.0f
};

// ---------------------------------------------------------------------------
// Pass 1: grid = 128*(b,h) x PARTS. Each block reduces GENES/PARTS genes.
//   A_n = sum_i K_i^n,  B_n = sum_i K_i^n * V_i
//   K_i = x[b,i]*WK[h,i], V_i = x[b,i]*WV[h,i].
// Stores A_n/n!, B_n/n! partials; pass 2 sums the PARTS partials.
// ---------------------------------------------------------------------------
__global__ void __launch_bounds__(256)
moments_kernel(const float* __restrict__ x,
               const float* __restrict__ WK,
               const float* __restrict__ WV)
{
    const int bh   = blockIdx.x >> 2;       // PARTS == 4
    const int part = blockIdx.x & 3;
    const int b    = bh >> 3;
    const int h    = bh & 7;
    const int base = part * (GENES / PARTS);

    const float* __restrict__ xb = x  + b * GENES + base;
    const float* __restrict__ wk = WK + h * GENES + base;
    const float* __restrict__ wv = WV + h * GENES + base;

    float A[NP], Bm[NP];
#pragma unroll
    for (int n = 0; n < NP; n++) { A[n] = 0.0f; Bm[n] = 0.0f; }

    // GENES/PARTS/256 = 2 elements per thread, independent chains (ILP=2)
#pragma unroll
    for (int e = 0; e < GENES / PARTS / 256; e++) {
        const int i  = threadIdx.x + e * 256;
        const float xi = xb[i];
        const float k  = xi * wk[i];
        const float v  = xi * wv[i];
        float p = 1.0f;
#pragma unroll
        for (int n = 0; n < NP; n++) {
            A[n]  += p;
            Bm[n]  = fmaf(p, v, Bm[n]);
            p     *= k;
        }
    }

    // Warp butterfly reduction
#pragma unroll
    for (int n = 0; n < NP; n++) {
#pragma unroll
        for (int off = 16; off > 0; off >>= 1) {
            A[n]  += __shfl_xor_sync(0xFFFFFFFFu, A[n],  off);
            Bm[n] += __shfl_xor_sync(0xFFFFFFFFu, Bm[n], off);
        }
    }

    __shared__ float sA[8][NP];
    __shared__ float sB[8][NP];
    const int w    = threadIdx.x >> 5;
    const int lane = threadIdx.x & 31;
    if (lane == 0) {
#pragma unroll
        for (int n = 0; n < NP; n++) { sA[w][n] = A[n]; sB[w][n] = Bm[n]; }
    }
    __syncthreads();

    if (threadIdx.x < NP) {
        const int n = threadIdx.x;
        float a = 0.0f, bb = 0.0f;
#pragma unroll
        for (int ww = 0; ww < 8; ww++) { a += sA[ww][n]; bb += sB[ww][n]; }
        const int idx = (bh * NP + n) * PARTS + part;
        g_momA[idx] = a  * c_invfact[n];
        g_momB[idx] = bb * c_invfact[n];
    }
}

// ---------------------------------------------------------------------------
// Pass 2: grid = 1024 (= BATCH * GENES/32). Block = 8 warps.
// Warp w handles head w for 32 consecutive genes (lane = gene offset).
//   q  = x[b,g]*WQ[h,g]
//   P0 = sum_n (A_n/n!) q^n ; P1 = sum_n (B_n/n!) q^n   (Horner)
//   z  = (P1 - exp(q*K_g)*V_g) / P0
//   out[b,g] = sum_h z_h * W0[h]   (cross-warp smem reduction)
// ---------------------------------------------------------------------------
__global__ void __launch_bounds__(256)
attn_out_kernel(const float* __restrict__ x,
                const float* __restrict__ WQ,
                const float* __restrict__ WK,
                const float* __restrict__ WV,
                const float* __restrict__ W0,
                float* __restrict__ out)
{
    const int b    = blockIdx.x >> 6;           // 16 batches
    const int g0   = (blockIdx.x & 63) << 5;    // 64 gene-groups of 32
    const int warp = threadIdx.x >> 5;          // head
    const int lane = threadIdx.x & 31;

    __shared__ float sA[HEADS][NP];
    __shared__ float sB[HEADS][NP];
    __shared__ float sz[HEADS][32];

    // Stage summed moments: 104 loader threads, each sums PARTS partials
    if (threadIdx.x < HEADS * NP) {
        const int h = threadIdx.x / NP;
        const int n = threadIdx.x % NP;
        const int base = ((b * HEADS + h) * NP + n) * PARTS;
        float a = 0.0f, bb = 0.0f;
#pragma unroll
        for (int p = 0; p < PARTS; p++) {
            a  += g_momA[base + p];
            bb += g_momB[base + p];
        }
        sA[h][n] = a;
        sB[h][n] = bb;
    }
    __syncthreads();

    const int h = warp;
    const int g = g0 + lane;

    const float xg = x[b * GENES + g];
    const float q  = xg * WQ[h * GENES + g];
    const float kg = xg * WK[h * GENES + g];
    const float vg = xg * WV[h * GENES + g];

    float P0 = sA[h][NP - 1];
    float P1 = sB[h][NP - 1];
#pragma unroll
    for (int n = NP - 2; n >= 0; n--) {
        P0 = fmaf(P0, q, sA[h][n]);
        P1 = fmaf(P1, q, sB[h][n]);
    }

    const float e = __expf(q * kg);               // exact diagonal correction
    const float z = __fdividef(P1 - e * vg, P0);

    sz[h][lane] = z * W0[h];
    __syncthreads();

    if (warp == 0) {
        float acc = 0.0f;
#pragma unroll
        for (int hh = 0; hh < HEADS; hh++) acc += sz[hh][lane];
        out[b * GENES + g0 + lane] = acc;
    }
}

// ---------------------------------------------------------------------------
extern "C" void kernel_launch(void* const* d_in, const int* in_sizes, int n_in,
                              void* d_out, int out_size)
{
    const float* x  = (const float*)d_in[0];
    const float* WQ = (const float*)d_in[1];
    const float* WK = (const float*)d_in[2];
    const float* WV = (const float*)d_in[3];
    const float* W0 = (const float*)d_in[4];
    float* out = (float*)d_out;

    moments_kernel<<<BATCH * HEADS * PARTS, 256>>>(x, WK, WV);
    attn_out_kernel<<<(BATCH * GENES) / 32, 256>>>(x, WQ, WK, WV, W0, out);
}

// round 3
// speedup vs baseline: 1.3652x; 1.2163x over previous
#include <cuda_runtime.h>

#define GENES 2048
#define HEADS 8
#define BATCH 16
#define NP 10          // Taylor moments: powers 0..9 (error < 2e-9 at |s|<=0.6)

// L2 scratch: per-(b,h): NP A-moments then NP B-moments, pre-scaled by 1/n!
__device__ float g_mom[BATCH * HEADS * 2 * NP];

__constant__ float c_invfact[NP] = {
    1.0f, 1.0f, 0.5f,
    1.0f / 6.0f, 1.0f / 24.0f, 1.0f / 120.0f,
    1.0f / 720.0f, 1.0f / 5040.0f, 1.0f / 40320.0f,
    1.0f / 362880.0f
};

// ---------------------------------------------------------------------------
// One fused kernel. Cluster of 8 CTAs = one batch (CTA rank = head).
// Phase 1: CTA (b,h) computes A_n = sum_i K_i^n, B_n = sum_i K_i^n V_i over
//          all 2048 genes (K_i = x*WK, V_i = x*WV), writes scaled moments to L2.
// barrier.cluster
// Phase 2: CTA rank h handles genes [h*256, h*256+256), one thread per gene:
//          per head, Horner-evaluate P0/P1 at q, exact-exp diagonal fixup,
//          combine with W0, write output. No second launch.
// ---------------------------------------------------------------------------
__global__ void __launch_bounds__(256, 1) __cluster_dims__(HEADS, 1, 1)
fused_attn_kernel(const float* __restrict__ x,
                  const float* __restrict__ WQ,
                  const float* __restrict__ WK,
                  const float* __restrict__ WV,
                  const float* __restrict__ W0,
                  float* __restrict__ out)
{
    const int b   = blockIdx.x >> 3;     // batch  (16 clusters)
    const int h   = blockIdx.x & 7;      // head = cluster rank
    const int tid = threadIdx.x;

    __shared__ float sRed[8][2 * NP];    // per-warp partial moments
    __shared__ float sA[HEADS][NP];      // staged moments for phase 2
    __shared__ float sB[HEADS][NP];
    __shared__ float sW0[HEADS];

    const float* __restrict__ xb = x + b * GENES;

    // ---------------- Phase 1: moments for (b, h) ----------------
    {
        const float* __restrict__ wk = WK + h * GENES;
        const float* __restrict__ wv = WV + h * GENES;

        float A[NP], Bm[NP];
#pragma unroll
        for (int n = 0; n < NP; n++) { A[n] = 0.0f; Bm[n] = 0.0f; }

#pragma unroll
        for (int e = 0; e < GENES / 256; e++) {
            const int i  = tid + e * 256;
            const float xi = xb[i];
            const float k  = xi * wk[i];
            const float v  = xi * wv[i];
            float p = 1.0f;
#pragma unroll
            for (int n = 0; n < NP; n++) {
                A[n]  += p;
                Bm[n]  = fmaf(p, v, Bm[n]);
                p     *= k;
            }
        }

        // Warp butterfly reduction
#pragma unroll
        for (int n = 0; n < NP; n++) {
#pragma unroll
            for (int off = 16; off > 0; off >>= 1) {
                A[n]  += __shfl_xor_sync(0xFFFFFFFFu, A[n],  off);
                Bm[n] += __shfl_xor_sync(0xFFFFFFFFu, Bm[n], off);
            }
        }

        const int w    = tid >> 5;
        const int lane = tid & 31;
        if (lane == 0) {
#pragma unroll
            for (int n = 0; n < NP; n++) {
                sRed[w][n]      = A[n];
                sRed[w][NP + n] = Bm[n];
            }
        }
        __syncthreads();

        if (tid < 2 * NP) {
            float s = 0.0f;
#pragma unroll
            for (int ww = 0; ww < 8; ww++) s += sRed[ww][tid];
            const int n = (tid < NP) ? tid : (tid - NP);
            g_mom[(b * HEADS + h) * 2 * NP + tid] = s * c_invfact[n];
            __threadfence();   // make L2 writes visible cluster-wide
        }
    }

    // ---------------- Cluster barrier (replaces 2nd kernel launch) ----------
    asm volatile("barrier.cluster.arrive.aligned;" ::: "memory");
    asm volatile("barrier.cluster.wait.aligned;"   ::: "memory");

    // ---------------- Phase 2: outputs for genes [h*256, h*256+256) ---------
    if (tid < HEADS * NP) {
        const int hh = tid / NP;
        const int n  = tid % NP;
        const int base = (b * HEADS + hh) * 2 * NP;
        sA[hh][n] = g_mom[base + n];
        sB[hh][n] = g_mom[base + NP + n];
    }
    if (tid < HEADS) sW0[tid] = W0[tid];
    __syncthreads();

    const int g   = h * 256 + tid;       // this CTA's gene slice
    const float xg = xb[g];
    float acc = 0.0f;

#pragma unroll
    for (int hh = 0; hh < HEADS; hh++) {
        const float q  = xg * WQ[hh * GENES + g];
        const float kg = xg * WK[hh * GENES + g];
        const float vg = xg * WV[hh * GENES + g];

        float P0 = sA[hh][NP - 1];
        float P1 = sB[hh][NP - 1];
#pragma unroll
        for (int n = NP - 2; n >= 0; n--) {
            P0 = fmaf(P0, q, sA[hh][n]);
            P1 = fmaf(P1, q, sB[hh][n]);
        }

        const float e = __expf(q * kg);            // exact diagonal correction
        const float z = __fdividef(P1 - e * vg, P0);
        acc = fmaf(z, sW0[hh], acc);
    }

    out[b * GENES + g] = acc;
}

// ---------------------------------------------------------------------------
extern "C" void kernel_launch(void* const* d_in, const int* in_sizes, int n_in,
                              void* d_out, int out_size)
{
    const float* x  = (const float*)d_in[0];
    const float* WQ = (const float*)d_in[1];
    const float* WK = (const float*)d_in[2];
    const float* WV = (const float*)d_in[3];
    const float* W0 = (const float*)d_in[4];
    float* out = (float*)d_out;

    fused_attn_kernel<<<BATCH * HEADS, 256>>>(x, WQ, WK, WV, W0, out);
}